// round 13
// baseline (speedup 1.0000x reference)
#include <cuda_runtime.h>
#include <cuda_fp16.h>
#include <math.h>

#define NN 50000
#define EE 1600000
#define E4 (EE / 4)            // 400000 int4 items
#define FDIM 128
#define NHEAD 4
#define SCAN_BS 256
#define SCAN_NB ((NN + SCAN_BS - 1) / SCAN_BS)   // 196
#define CSR_NB 592             // 4 CTAs/SM * 148 SMs -> guaranteed wave-1 resident
#define CSR_T (CSR_NB * 256)   // 151552 threads; ceil(E4/CSR_T)=3 items/thread

// ---------------- scratch (device globals, no allocation) ----------------
__device__ __half d_fth[NN * FDIM]; // transposed per-node features fp16: [n][d*4+h]
__device__ __half d_xh[NN * FDIM];  // inter-layer activations fp16: [n][h*32+d]
__device__ float d_el[NN * NHEAD];
__device__ float d_er[NN * NHEAD];
__device__ int   d_cnt[NN];         // zero-init; self-cleaned each run
__device__ int   d_rowptr[NN + 1];
__device__ int   d_esrc[EE];
__device__ int   d_bsum[SCAN_NB];
__device__ int   d_boff[SCAN_NB];
__device__ int   d_bar1;            // grid barrier 1 arrive counter
__device__ int   d_bar2;            // grid barrier 2 arrive counter
__device__ int   d_scan_ctr;        // ticket: which scan block arrived last
__device__ int   d_scan_flag;       // boff published flag
__device__ int   d_done_ctr;        // last finisher resets all state

// ---------------- fused CSR build: count -> scan -> scatter, one kernel ----------------
// Tickets and dst stay IN REGISTERS across the grid barriers: no d_eoff array,
// dst read once, no inter-kernel launch gaps. 592 blocks, all resident (deadlock-free).
__global__ __launch_bounds__(256, 4) void csr_fused_kernel(const int4* __restrict__ src4,
                                                           const int4* __restrict__ dst4) {
    __shared__ int sh[SCAN_BS];
    __shared__ bool s_last;
    __shared__ int s_boff;
    int b = blockIdx.x, t = threadIdx.x;
    int gid = b * 256 + t;

    // ---- phase 1: count + ticket capture (kept in registers) ----
    int4 dd[3], oo[3];
#pragma unroll
    for (int it = 0; it < 3; it++) {
        int idx = gid + it * CSR_T;
        if (idx < E4) {
            int4 d = dst4[idx];
            int4 o;
            o.x = atomicAdd(&d_cnt[d.x], 1);
            o.y = atomicAdd(&d_cnt[d.y], 1);
            o.z = atomicAdd(&d_cnt[d.z], 1);
            o.w = atomicAdd(&d_cnt[d.w], 1);
            dd[it] = d;
            oo[it] = o;
        }
    }

    // ---- grid barrier 1 (all counts visible) ----
    __threadfence();
    __syncthreads();
    if (t == 0) {
        atomicAdd(&d_bar1, 1);
        volatile int* vb = &d_bar1;
        while (*vb < CSR_NB) {}
    }
    __syncthreads();
    __threadfence();

    // ---- phase 2: scan + emit rowptr (blocks 0..195 only) ----
    if (b < SCAN_NB) {
        int i = b * SCAN_BS + t;
        int v = (i < NN) ? d_cnt[i] : 0;
        if (i < NN) d_cnt[i] = 0;        // self-clean for next replay
        sh[t] = v;
        __syncthreads();
        for (int d = 1; d < SCAN_BS; d <<= 1) {
            int x = sh[t];
            int add = (t >= d) ? sh[t - d] : 0;
            __syncthreads();
            sh[t] = x + add;
            __syncthreads();
        }
        int incl = sh[t];
        int total = sh[SCAN_BS - 1];

        volatile int* vflag = &d_scan_flag;
        if (t == 0) {
            d_bsum[b] = total;
            __threadfence();
            int ticket = atomicAdd(&d_scan_ctr, 1);
            s_last = (ticket == SCAN_NB - 1);
        }
        __syncthreads();

        if (s_last) {
            __syncthreads();
            int x = (t < SCAN_NB) ? d_bsum[t] : 0;
            int orig = x;
            sh[t] = x;
            __syncthreads();
            for (int d = 1; d < SCAN_BS; d <<= 1) {
                int y = sh[t];
                int add = (t >= d) ? sh[t - d] : 0;
                __syncthreads();
                sh[t] = y + add;
                __syncthreads();
            }
            if (t < SCAN_NB) d_boff[t] = sh[t] - orig;   // exclusive
            if (t == SCAN_NB - 1) d_rowptr[NN] = sh[t];
            __threadfence();
            if (t == 0) *vflag = 1;
        }

        if (t == 0) {
            while (*vflag == 0) {}
            __threadfence();
            s_boff = d_boff[b];
        }
        __syncthreads();
        if (i < NN) d_rowptr[i] = s_boff + incl - v;    // exclusive prefix
        __threadfence();
    }

    // ---- grid barrier 2 (rowptr visible to everyone) ----
    __syncthreads();
    if (t == 0) {
        atomicAdd(&d_bar2, 1);
        volatile int* vb = &d_bar2;
        while (*vb < CSR_NB) {}
    }
    __syncthreads();
    __threadfence();

    // ---- phase 3: atomic-free scatter from register-held tickets ----
#pragma unroll
    for (int it = 0; it < 3; it++) {
        int idx = gid + it * CSR_T;
        if (idx < E4) {
            int4 s = src4[idx];
            int4 d = dd[it];
            int4 o = oo[it];
            d_esrc[d_rowptr[d.x] + o.x] = s.x;
            d_esrc[d_rowptr[d.y] + o.y] = s.y;
            d_esrc[d_rowptr[d.z] + o.z] = s.z;
            d_esrc[d_rowptr[d.w] + o.w] = s.w;
        }
    }

    // ---- reset barrier/ticket state for the next graph replay ----
    __threadfence();
    __syncthreads();
    if (t == 0) {
        int k = atomicAdd(&d_done_ctr, 1);
        if (k == CSR_NB - 1) {
            d_bar1 = 0;
            d_bar2 = 0;
            d_scan_ctr = 0;
            d_scan_flag = 0;
            d_done_ctr = 0;
        }
    }
}

// ---------------- tensor-core GEMM ----------------
__device__ __forceinline__ void mma16816(float* d,
                                         unsigned a0, unsigned a1, unsigned a2, unsigned a3,
                                         unsigned b0, unsigned b1) {
    asm volatile(
        "mma.sync.aligned.m16n8k16.row.col.f32.f16.f16.f32 "
        "{%0,%1,%2,%3}, {%4,%5,%6,%7}, {%8,%9}, {%0,%1,%2,%3};"
        : "+f"(d[0]), "+f"(d[1]), "+f"(d[2]), "+f"(d[3])
        : "r"(a0), "r"(a1), "r"(a2), "r"(a3), "r"(b0), "r"(b1));
}
__device__ __forceinline__ unsigned f2h2(float lo, float hi) {
    __half2 h = __floats2half2_rn(lo, hi);
    return *reinterpret_cast<unsigned*>(&h);
}

// ft = x @ W -> fp16 transposed [n][d*4+h], fused el/er (fp32), via HMMA m16n8k16.
// Block: 256 threads (8 warps), 128 rows/block, full N=128, K=128 (8 k-steps).
// __launch_bounds__(256, 2): cap regs at 128 so 2 CTAs fit per SM.
#define WSTRIDE 136
template <bool X_IS_HALF>
__global__ __launch_bounds__(256, 2) void gemm_tc_kernel(const float* __restrict__ xin,
                                                         const float* __restrict__ W,
                                                         const float* __restrict__ al,
                                                         const float* __restrict__ ar) {
    __shared__ __half Wt[128 * WSTRIDE];   // union: W^T fp16 [n][k], then per-warp staging
    __shared__ float sal[128], sar[128];
    int t = threadIdx.x;
    int w = t >> 5, l = t & 31;
    int g = l >> 2, tig = l & 3;
    int row0 = blockIdx.x * 128;

    // W fp32 [k][n] -> Wt fp16 [n][k] (coalesced global read)
#pragma unroll
    for (int i = 0; i < 64; i++) {
        int idx = t + 256 * i;
        int k = idx >> 7, n = idx & 127;
        Wt[n * WSTRIDE + k] = __float2half(W[idx]);
    }
    if (t < 128) sal[t] = al[t];
    else sar[t - 128] = ar[t - 128];
    __syncthreads();

    float acc[16][4];
#pragma unroll
    for (int nt = 0; nt < 16; nt++)
#pragma unroll
        for (int j = 0; j < 4; j++) acc[nt][j] = 0.f;

    int r1 = row0 + w * 16 + g;   // rows this thread's fragments cover
    int r2 = r1 + 8;
    bool ok1 = r1 < NN, ok2 = r2 < NN;

#pragma unroll
    for (int ks = 0; ks < 8; ks++) {
        int k0 = ks * 16 + 2 * tig;
        unsigned a0 = 0, a1 = 0, a2 = 0, a3 = 0;
        if (X_IS_HALF) {
            if (ok1) {
                a0 = *reinterpret_cast<const unsigned*>(&d_xh[r1 * 128 + k0]);
                a2 = *reinterpret_cast<const unsigned*>(&d_xh[r1 * 128 + k0 + 8]);
            }
            if (ok2) {
                a1 = *reinterpret_cast<const unsigned*>(&d_xh[r2 * 128 + k0]);
                a3 = *reinterpret_cast<const unsigned*>(&d_xh[r2 * 128 + k0 + 8]);
            }
        } else {
            if (ok1) {
                float2 f = *reinterpret_cast<const float2*>(&xin[r1 * 128 + k0]);
                a0 = f2h2(f.x, f.y);
                f = *reinterpret_cast<const float2*>(&xin[r1 * 128 + k0 + 8]);
                a2 = f2h2(f.x, f.y);
            }
            if (ok2) {
                float2 f = *reinterpret_cast<const float2*>(&xin[r2 * 128 + k0]);
                a1 = f2h2(f.x, f.y);
                f = *reinterpret_cast<const float2*>(&xin[r2 * 128 + k0 + 8]);
                a3 = f2h2(f.x, f.y);
            }
        }
#pragma unroll
        for (int nt = 0; nt < 16; nt++) {
            const __half* bp = &Wt[(nt * 8 + g) * WSTRIDE + k0];
            unsigned b0 = *reinterpret_cast<const unsigned*>(bp);
            unsigned b1 = *reinterpret_cast<const unsigned*>(bp + 8);
            mma16816(acc[nt], a0, a1, a2, a3, b0, b1);
        }
    }

    // fused el/er from fragments: col c = nt*8 + 2*tig (+1); head = nt>>2
    {
        float pll[4] = {0, 0, 0, 0}, plh[4] = {0, 0, 0, 0};
        float prl[4] = {0, 0, 0, 0}, prh[4] = {0, 0, 0, 0};
#pragma unroll
        for (int nt = 0; nt < 16; nt++) {
            int hh = nt >> 2;
            int c = nt * 8 + 2 * tig;
            float s0 = sal[c], s1 = sal[c + 1];
            float u0 = sar[c], u1 = sar[c + 1];
            pll[hh] += acc[nt][0] * s0 + acc[nt][1] * s1;
            plh[hh] += acc[nt][2] * s0 + acc[nt][3] * s1;
            prl[hh] += acc[nt][0] * u0 + acc[nt][1] * u1;
            prh[hh] += acc[nt][2] * u0 + acc[nt][3] * u1;
        }
#pragma unroll
        for (int o = 1; o <= 2; o <<= 1) {
#pragma unroll
            for (int hh = 0; hh < 4; hh++) {
                pll[hh] += __shfl_xor_sync(0xffffffffu, pll[hh], o);
                plh[hh] += __shfl_xor_sync(0xffffffffu, plh[hh], o);
                prl[hh] += __shfl_xor_sync(0xffffffffu, prl[hh], o);
                prh[hh] += __shfl_xor_sync(0xffffffffu, prh[hh], o);
            }
        }
        if (tig == 0) {
            if (ok1) {
                *reinterpret_cast<float4*>(&d_el[r1 * 4]) = make_float4(pll[0], pll[1], pll[2], pll[3]);
                *reinterpret_cast<float4*>(&d_er[r1 * 4]) = make_float4(prl[0], prl[1], prl[2], prl[3]);
            }
            if (ok2) {
                *reinterpret_cast<float4*>(&d_el[r2 * 4]) = make_float4(plh[0], plh[1], plh[2], plh[3]);
                *reinterpret_cast<float4*>(&d_er[r2 * 4]) = make_float4(prh[0], prh[1], prh[2], prh[3]);
            }
        }
    }

    // stage D (fp16) per warp, then write ft transposed [r][d*4+h]
    __syncthreads();   // all warps done reading Wt
    __half* stg = &Wt[w * 16 * WSTRIDE];
#pragma unroll
    for (int nt = 0; nt < 16; nt++) {
        int c = nt * 8 + 2 * tig;
        *reinterpret_cast<unsigned*>(&stg[g * WSTRIDE + c]) = f2h2(acc[nt][0], acc[nt][1]);
        *reinterpret_cast<unsigned*>(&stg[(g + 8) * WSTRIDE + c]) = f2h2(acc[nt][2], acc[nt][3]);
    }
    __syncwarp();
#pragma unroll
    for (int r = 0; r < 16; r++) {
        int rr = row0 + w * 16 + r;
        if (rr < NN) {
            __half v0 = stg[r * WSTRIDE + l];
            __half v1 = stg[r * WSTRIDE + 32 + l];
            __half v2 = stg[r * WSTRIDE + 64 + l];
            __half v3 = stg[r * WSTRIDE + 96 + l];
            __half2 p01 = __halves2half2(v0, v1);
            __half2 p23 = __halves2half2(v2, v3);
            uint2 o;
            o.x = *reinterpret_cast<unsigned*>(&p01);
            o.y = *reinterpret_cast<unsigned*>(&p23);
            *reinterpret_cast<uint2*>(&d_fth[rr * 128 + l * 4]) = o;
        }
    }
}

// ---------------- per-dst-node softmax + aggregation, single pass (no max) ----------------
// MODE 0: write ELU(result) as fp16 into d_xh ([n][h*32+d]). MODE 1: write mean over heads into out.
template <int MODE>
__global__ __launch_bounds__(256) void agg_kernel(const float* __restrict__ bias,
                                                  float* __restrict__ out) {
    __shared__ float4 sw[8][32];
    __shared__ int ss[8][32];
    int warp = threadIdx.x >> 5, lane = threadIdx.x & 31;
    int n = blockIdx.x * 8 + warp;
    if (n >= NN) return;
    int start = d_rowptr[n], end = d_rowptr[n + 1];
    float4 ern = *reinterpret_cast<const float4*>(&d_er[n * 4]);

    float acc0 = 0.f, acc1 = 0.f, acc2 = 0.f, acc3 = 0.f;
    float z0 = 0.f, z1 = 0.f, z2 = 0.f, z3 = 0.f;

    for (int c = start; c < end; c += 32) {
        int idx = c + lane;
        int s = 0;
        float4 w = make_float4(0.f, 0.f, 0.f, 0.f);
        if (idx < end) {
            s = d_esrc[idx];
            float4 e4 = *reinterpret_cast<const float4*>(&d_el[s * 4]);
            float e;
            e = e4.x + ern.x; e = e > 0.f ? e : 0.2f * e; w.x = __expf(e);
            e = e4.y + ern.y; e = e > 0.f ? e : 0.2f * e; w.y = __expf(e);
            e = e4.z + ern.z; e = e > 0.f ? e : 0.2f * e; w.z = __expf(e);
            e = e4.w + ern.w; e = e > 0.f ? e : 0.2f * e; w.w = __expf(e);
            z0 += w.x; z1 += w.y; z2 += w.z; z3 += w.w;
        }
        ss[warp][lane] = s;
        sw[warp][lane] = w;
        __syncwarp();
        int cnt = end - c; if (cnt > 32) cnt = 32;
        int j = 0;
        // 4-wide batches: 4 independent LDG.64 in flight before the FMAs
        for (; j + 4 <= cnt; j += 4) {
            int sa = ss[warp][j], sb = ss[warp][j + 1];
            int sc = ss[warp][j + 2], sd = ss[warp][j + 3];
            float4 wa = sw[warp][j], wb = sw[warp][j + 1];
            float4 wc = sw[warp][j + 2], wd = sw[warp][j + 3];
            uint2 fa = *reinterpret_cast<const uint2*>(&d_fth[sa * 128 + lane * 4]);
            uint2 fb = *reinterpret_cast<const uint2*>(&d_fth[sb * 128 + lane * 4]);
            uint2 fc = *reinterpret_cast<const uint2*>(&d_fth[sc * 128 + lane * 4]);
            uint2 fd = *reinterpret_cast<const uint2*>(&d_fth[sd * 128 + lane * 4]);
            float2 a01 = __half22float2(*reinterpret_cast<__half2*>(&fa.x));
            float2 a23 = __half22float2(*reinterpret_cast<__half2*>(&fa.y));
            float2 b01 = __half22float2(*reinterpret_cast<__half2*>(&fb.x));
            float2 b23 = __half22float2(*reinterpret_cast<__half2*>(&fb.y));
            float2 c01 = __half22float2(*reinterpret_cast<__half2*>(&fc.x));
            float2 c23 = __half22float2(*reinterpret_cast<__half2*>(&fc.y));
            float2 d01 = __half22float2(*reinterpret_cast<__half2*>(&fd.x));
            float2 d23 = __half22float2(*reinterpret_cast<__half2*>(&fd.y));
            acc0 += wa.x * a01.x; acc1 += wa.y * a01.y; acc2 += wa.z * a23.x; acc3 += wa.w * a23.y;
            acc0 += wb.x * b01.x; acc1 += wb.y * b01.y; acc2 += wb.z * b23.x; acc3 += wb.w * b23.y;
            acc0 += wc.x * c01.x; acc1 += wc.y * c01.y; acc2 += wc.z * c23.x; acc3 += wc.w * c23.y;
            acc0 += wd.x * d01.x; acc1 += wd.y * d01.y; acc2 += wd.z * d23.x; acc3 += wd.w * d23.y;
        }
        for (; j < cnt; j++) {
            int s2 = ss[warp][j];
            float4 wv = sw[warp][j];
            uint2 f = *reinterpret_cast<const uint2*>(&d_fth[s2 * 128 + lane * 4]);
            float2 f01 = __half22float2(*reinterpret_cast<__half2*>(&f.x));
            float2 f23 = __half22float2(*reinterpret_cast<__half2*>(&f.y));
            acc0 += wv.x * f01.x; acc1 += wv.y * f01.y;
            acc2 += wv.z * f23.x; acc3 += wv.w * f23.y;
        }
        __syncwarp();
    }
#pragma unroll
    for (int o = 16; o > 0; o >>= 1) {
        z0 += __shfl_xor_sync(0xffffffffu, z0, o);
        z1 += __shfl_xor_sync(0xffffffffu, z1, o);
        z2 += __shfl_xor_sync(0xffffffffu, z2, o);
        z3 += __shfl_xor_sync(0xffffffffu, z3, o);
    }

    float v0 = (z0 > 0.f ? acc0 / z0 : 0.f) + bias[0 * 32 + lane];
    float v1 = (z1 > 0.f ? acc1 / z1 : 0.f) + bias[1 * 32 + lane];
    float v2 = (z2 > 0.f ? acc2 / z2 : 0.f) + bias[2 * 32 + lane];
    float v3 = (z3 > 0.f ? acc3 / z3 : 0.f) + bias[3 * 32 + lane];

    if (MODE == 0) {
        v0 = v0 > 0.f ? v0 : __expf(v0) - 1.f;
        v1 = v1 > 0.f ? v1 : __expf(v1) - 1.f;
        v2 = v2 > 0.f ? v2 : __expf(v2) - 1.f;
        v3 = v3 > 0.f ? v3 : __expf(v3) - 1.f;
        d_xh[n * 128 + 0 * 32 + lane] = __float2half(v0);
        d_xh[n * 128 + 1 * 32 + lane] = __float2half(v1);
        d_xh[n * 128 + 2 * 32 + lane] = __float2half(v2);
        d_xh[n * 128 + 3 * 32 + lane] = __float2half(v3);
    } else {
        out[n * 32 + lane] = (v0 + v1 + v2 + v3) * 0.25f;
    }
}

// ---------------- launch ----------------
extern "C" void kernel_launch(void* const* d_in, const int* in_sizes, int n_in,
                              void* d_out, int out_size) {
    const float* h   = (const float*)d_in[0];
    const int*   src = (const int*)d_in[1];
    const int*   dst = (const int*)d_in[2];
    const float* W1  = (const float*)d_in[3];
    const float* al1 = (const float*)d_in[4];
    const float* ar1 = (const float*)d_in[5];
    const float* b1  = (const float*)d_in[6];
    const float* W2  = (const float*)d_in[7];
    const float* al2 = (const float*)d_in[8];
    const float* ar2 = (const float*)d_in[9];
    const float* b2  = (const float*)d_in[10];
    const float* W3  = (const float*)d_in[11];
    const float* al3 = (const float*)d_in[12];
    const float* ar3 = (const float*)d_in[13];
    const float* b3  = (const float*)d_in[14];
    float* out = (float*)d_out;

    const int GEMM_BLOCKS = (NN + 127) / 128;
    const int NODE_BLOCKS = (NN + 7) / 8;

    // CSR build: one fused grid-resident kernel (count -> scan -> scatter)
    csr_fused_kernel<<<CSR_NB, 256>>>((const int4*)src, (const int4*)dst);

    // layer 1
    gemm_tc_kernel<false><<<GEMM_BLOCKS, 256>>>(h, W1, al1, ar1);
    agg_kernel<0><<<NODE_BLOCKS, 256>>>(b1, nullptr);

    // layer 2
    gemm_tc_kernel<true><<<GEMM_BLOCKS, 256>>>(nullptr, W2, al2, ar2);
    agg_kernel<0><<<NODE_BLOCKS, 256>>>(b2, nullptr);

    // layer 3
    gemm_tc_kernel<true><<<GEMM_BLOCKS, 256>>>(nullptr, W3, al3, ar3);
    agg_kernel<1><<<NODE_BLOCKS, 256>>>(b3, out);
}

// round 14
// speedup vs baseline: 1.0667x; 1.0667x over previous
#include <cuda_runtime.h>
#include <cuda_fp16.h>
#include <math.h>

#define NN 50000
#define EE 1600000
#define FDIM 128
#define NHEAD 4
#define SCAN_BS 256
#define SCAN_NB ((NN + SCAN_BS - 1) / SCAN_BS)   // 196

// ---------------- scratch (device globals, no allocation) ----------------
__device__ __half d_fth[NN * FDIM]; // transposed per-node features fp16: [n][d*4+h]
__device__ __half d_xh[NN * FDIM];  // inter-layer activations fp16: [n][h*32+d]
__device__ __half d_wh[3][FDIM * FDIM]; // fp16 W^T per layer: [n][k]
__device__ float d_el[NN * NHEAD];
__device__ float d_er[NN * NHEAD];
__device__ int   d_cnt[NN];         // zero-init; self-cleaned each run
__device__ int   d_rowptr[NN + 1];
__device__ int   d_esrc[EE];
__device__ int   d_eoff[EE];        // per-edge ticket (local offset within dst's segment)
__device__ int   d_bsum[SCAN_NB];
__device__ int   d_boff[SCAN_NB];
__device__ int   d_scan_ctr;
__device__ int   d_done_ctr;
__device__ int   d_scan_flag;

// ---------------- W preconversion: fp32 [k][n] -> fp16 transposed [n][k], all 3 layers ----------------
__global__ void wconv_kernel(const float* __restrict__ W1,
                             const float* __restrict__ W2,
                             const float* __restrict__ W3) {
    int idx = blockIdx.x * blockDim.x + threadIdx.x;   // 0 .. 3*16384-1
    if (idx < 3 * FDIM * FDIM) {
        int layer = idx >> 14;
        int rem = idx & 16383;
        int k = rem >> 7, n = rem & 127;
        const float* W = (layer == 0) ? W1 : (layer == 1) ? W2 : W3;
        d_wh[layer][n * FDIM + k] = __float2half(W[rem]);
    }
}

// ---------------- CSR build ----------------
// Count + ticket capture: the atomicAdd return value IS the edge's local
// offset within its destination segment; store it so scatter needs no atomics.
__global__ void count_kernel(const int4* __restrict__ dst4) {
    int i = blockIdx.x * blockDim.x + threadIdx.x;
    if (i < EE / 4) {
        int4 d = dst4[i];
        int4 o;
        o.x = atomicAdd(&d_cnt[d.x], 1);
        o.y = atomicAdd(&d_cnt[d.y], 1);
        o.z = atomicAdd(&d_cnt[d.z], 1);
        o.w = atomicAdd(&d_cnt[d.w], 1);
        reinterpret_cast<int4*>(d_eoff)[i] = o;
    }
}

// Fused scan+emit, grid-resident (196 blocks all fit in wave 1).
__global__ __launch_bounds__(SCAN_BS) void csr_scan_emit_kernel() {
    __shared__ int sh[SCAN_BS];
    __shared__ bool s_last;
    __shared__ int s_boff;
    int b = blockIdx.x, t = threadIdx.x;
    int i = b * SCAN_BS + t;
    int v = (i < NN) ? d_cnt[i] : 0;
    if (i < NN) d_cnt[i] = 0;        // self-clean for the next replay

    sh[t] = v;
    __syncthreads();
    for (int d = 1; d < SCAN_BS; d <<= 1) {
        int x = sh[t];
        int add = (t >= d) ? sh[t - d] : 0;
        __syncthreads();
        sh[t] = x + add;
        __syncthreads();
    }
    int incl = sh[t];
    int total = sh[SCAN_BS - 1];

    volatile int* vflag = &d_scan_flag;
    if (t == 0) {
        d_bsum[b] = total;
        __threadfence();
        int ticket = atomicAdd(&d_scan_ctr, 1);
        s_last = (ticket == SCAN_NB - 1);
    }
    __syncthreads();

    if (s_last) {
        __syncthreads();
        int x = (t < SCAN_NB) ? d_bsum[t] : 0;
        int orig = x;
        sh[t] = x;
        __syncthreads();
        for (int d = 1; d < SCAN_BS; d <<= 1) {
            int y = sh[t];
            int add = (t >= d) ? sh[t - d] : 0;
            __syncthreads();
            sh[t] = y + add;
            __syncthreads();
        }
        if (t < SCAN_NB) d_boff[t] = sh[t] - orig;   // exclusive
        if (t == SCAN_NB - 1) d_rowptr[NN] = sh[t];
        __threadfence();
        if (t == 0) *vflag = 1;
    }

    if (t == 0) {
        while (*vflag == 0) {}
        __threadfence();
        s_boff = d_boff[b];
    }
    __syncthreads();
    if (i < NN) d_rowptr[i] = s_boff + incl - v;    // exclusive prefix
    __syncthreads();
    if (t == 0) {
        int ticket2 = atomicAdd(&d_done_ctr, 1);
        if (ticket2 == SCAN_NB - 1) {
            d_scan_flag = 0;
            d_scan_ctr = 0;
            d_done_ctr = 0;
        }
    }
}

// Atomic-free scatter: destination slot = rowptr[dst] + ticket.
__global__ void scatter_kernel(const int4* __restrict__ src4, const int4* __restrict__ dst4) {
    int i = blockIdx.x * blockDim.x + threadIdx.x;
    if (i < EE / 4) {
        int4 s = src4[i];
        int4 d = dst4[i];
        int4 o = reinterpret_cast<const int4*>(d_eoff)[i];
        d_esrc[d_rowptr[d.x] + o.x] = s.x;
        d_esrc[d_rowptr[d.y] + o.y] = s.y;
        d_esrc[d_rowptr[d.z] + o.z] = s.z;
        d_esrc[d_rowptr[d.w] + o.w] = s.w;
    }
}

// ---------------- tensor-core GEMM ----------------
__device__ __forceinline__ void mma16816(float* d,
                                         unsigned a0, unsigned a1, unsigned a2, unsigned a3,
                                         unsigned b0, unsigned b1) {
    asm volatile(
        "mma.sync.aligned.m16n8k16.row.col.f32.f16.f16.f32 "
        "{%0,%1,%2,%3}, {%4,%5,%6,%7}, {%8,%9}, {%0,%1,%2,%3};"
        : "+f"(d[0]), "+f"(d[1]), "+f"(d[2]), "+f"(d[3])
        : "r"(a0), "r"(a1), "r"(a2), "r"(a3), "r"(b0), "r"(b1));
}
__device__ __forceinline__ unsigned f2h2(float lo, float hi) {
    __half2 h = __floats2half2_rn(lo, hi);
    return *reinterpret_cast<unsigned*>(&h);
}

// ft = x @ W -> fp16 transposed [n][d*4+h], fused el/er (fp32), via HMMA m16n8k16.
// W is PRE-CONVERTED fp16 [n][k] in gmem (L2-resident): prologue is a pure
// fp16 copy (8x LDG.128 + 8x STS.128 per thread) instead of 64x load+cvt+store.
#define WSTRIDE 136
template <bool X_IS_HALF>
__global__ __launch_bounds__(256, 2) void gemm_tc_kernel(const float* __restrict__ xin,
                                                         const __half* __restrict__ Wh,
                                                         const float* __restrict__ al,
                                                         const float* __restrict__ ar) {
    __shared__ __half Wt[128 * WSTRIDE];   // union: W^T fp16 [n][k], then per-warp staging
    __shared__ float sal[128], sar[128];
    int t = threadIdx.x;
    int w = t >> 5, l = t & 31;
    int g = l >> 2, tig = l & 3;
    int row0 = blockIdx.x * 128;

    // fp16 W^T copy: 2048 uint4 (8 halfs each); e -> n = (e*8)>>7, k = (e*8)&127
#pragma unroll
    for (int i = 0; i < 8; i++) {
        int e = t + 256 * i;
        int n = e >> 4;             // 16 uint4 per n-row
        int k8 = (e & 15) << 3;     // k in units of 8
        uint4 v = reinterpret_cast<const uint4*>(Wh)[e];
        *reinterpret_cast<uint4*>(&Wt[n * WSTRIDE + k8]) = v;
    }
    if (t < 128) sal[t] = al[t];
    else sar[t - 128] = ar[t - 128];
    __syncthreads();

    float acc[16][4];
#pragma unroll
    for (int nt = 0; nt < 16; nt++)
#pragma unroll
        for (int j = 0; j < 4; j++) acc[nt][j] = 0.f;

    int r1 = row0 + w * 16 + g;   // rows this thread's fragments cover
    int r2 = r1 + 8;
    bool ok1 = r1 < NN, ok2 = r2 < NN;

#pragma unroll
    for (int ks = 0; ks < 8; ks++) {
        int k0 = ks * 16 + 2 * tig;
        unsigned a0 = 0, a1 = 0, a2 = 0, a3 = 0;
        if (X_IS_HALF) {
            if (ok1) {
                a0 = *reinterpret_cast<const unsigned*>(&d_xh[r1 * 128 + k0]);
                a2 = *reinterpret_cast<const unsigned*>(&d_xh[r1 * 128 + k0 + 8]);
            }
            if (ok2) {
                a1 = *reinterpret_cast<const unsigned*>(&d_xh[r2 * 128 + k0]);
                a3 = *reinterpret_cast<const unsigned*>(&d_xh[r2 * 128 + k0 + 8]);
            }
        } else {
            if (ok1) {
                float2 f = *reinterpret_cast<const float2*>(&xin[r1 * 128 + k0]);
                a0 = f2h2(f.x, f.y);
                f = *reinterpret_cast<const float2*>(&xin[r1 * 128 + k0 + 8]);
                a2 = f2h2(f.x, f.y);
            }
            if (ok2) {
                float2 f = *reinterpret_cast<const float2*>(&xin[r2 * 128 + k0]);
                a1 = f2h2(f.x, f.y);
                f = *reinterpret_cast<const float2*>(&xin[r2 * 128 + k0 + 8]);
                a3 = f2h2(f.x, f.y);
            }
        }
#pragma unroll
        for (int nt = 0; nt < 16; nt++) {
            const __half* bp = &Wt[(nt * 8 + g) * WSTRIDE + k0];
            unsigned b0 = *reinterpret_cast<const unsigned*>(bp);
            unsigned b1 = *reinterpret_cast<const unsigned*>(bp + 8);
            mma16816(acc[nt], a0, a1, a2, a3, b0, b1);
        }
    }

    // fused el/er from fragments: col c = nt*8 + 2*tig (+1); head = nt>>2
    {
        float pll[4] = {0, 0, 0, 0}, plh[4] = {0, 0, 0, 0};
        float prl[4] = {0, 0, 0, 0}, prh[4] = {0, 0, 0, 0};
#pragma unroll
        for (int nt = 0; nt < 16; nt++) {
            int hh = nt >> 2;
            int c = nt * 8 + 2 * tig;
            float s0 = sal[c], s1 = sal[c + 1];
            float u0 = sar[c], u1 = sar[c + 1];
            pll[hh] += acc[nt][0] * s0 + acc[nt][1] * s1;
            plh[hh] += acc[nt][2] * s0 + acc[nt][3] * s1;
            prl[hh] += acc[nt][0] * u0 + acc[nt][1] * u1;
            prh[hh] += acc[nt][2] * u0 + acc[nt][3] * u1;
        }
#pragma unroll
        for (int o = 1; o <= 2; o <<= 1) {
#pragma unroll
            for (int hh = 0; hh < 4; hh++) {
                pll[hh] += __shfl_xor_sync(0xffffffffu, pll[hh], o);
                plh[hh] += __shfl_xor_sync(0xffffffffu, plh[hh], o);
                prl[hh] += __shfl_xor_sync(0xffffffffu, prl[hh], o);
                prh[hh] += __shfl_xor_sync(0xffffffffu, prh[hh], o);
            }
        }
        if (tig == 0) {
            if (ok1) {
                *reinterpret_cast<float4*>(&d_el[r1 * 4]) = make_float4(pll[0], pll[1], pll[2], pll[3]);
                *reinterpret_cast<float4*>(&d_er[r1 * 4]) = make_float4(prl[0], prl[1], prl[2], prl[3]);
            }
            if (ok2) {
                *reinterpret_cast<float4*>(&d_el[r2 * 4]) = make_float4(plh[0], plh[1], plh[2], plh[3]);
                *reinterpret_cast<float4*>(&d_er[r2 * 4]) = make_float4(prh[0], prh[1], prh[2], prh[3]);
            }
        }
    }

    // stage D (fp16) per warp, then write ft transposed [r][d*4+h]
    __syncthreads();   // all warps done reading Wt
    __half* stg = &Wt[w * 16 * WSTRIDE];
#pragma unroll
    for (int nt = 0; nt < 16; nt++) {
        int c = nt * 8 + 2 * tig;
        *reinterpret_cast<unsigned*>(&stg[g * WSTRIDE + c]) = f2h2(acc[nt][0], acc[nt][1]);
        *reinterpret_cast<unsigned*>(&stg[(g + 8) * WSTRIDE + c]) = f2h2(acc[nt][2], acc[nt][3]);
    }
    __syncwarp();
#pragma unroll
    for (int r = 0; r < 16; r++) {
        int rr = row0 + w * 16 + r;
        if (rr < NN) {
            __half v0 = stg[r * WSTRIDE + l];
            __half v1 = stg[r * WSTRIDE + 32 + l];
            __half v2 = stg[r * WSTRIDE + 64 + l];
            __half v3 = stg[r * WSTRIDE + 96 + l];
            __half2 p01 = __halves2half2(v0, v1);
            __half2 p23 = __halves2half2(v2, v3);
            uint2 o;
            o.x = *reinterpret_cast<unsigned*>(&p01);
            o.y = *reinterpret_cast<unsigned*>(&p23);
            *reinterpret_cast<uint2*>(&d_fth[rr * 128 + l * 4]) = o;
        }
    }
}

// ---------------- per-dst-node softmax + aggregation, single pass (no max) ----------------
// MODE 0: write ELU(result) as fp16 into d_xh ([n][h*32+d]). MODE 1: write mean over heads into out.
template <int MODE>
__global__ __launch_bounds__(256) void agg_kernel(const float* __restrict__ bias,
                                                  float* __restrict__ out) {
    __shared__ float4 sw[8][32];
    __shared__ int ss[8][32];
    int warp = threadIdx.x >> 5, lane = threadIdx.x & 31;
    int n = blockIdx.x * 8 + warp;
    if (n >= NN) return;
    int start = d_rowptr[n], end = d_rowptr[n + 1];
    float4 ern = *reinterpret_cast<const float4*>(&d_er[n * 4]);

    float acc0 = 0.f, acc1 = 0.f, acc2 = 0.f, acc3 = 0.f;
    float z0 = 0.f, z1 = 0.f, z2 = 0.f, z3 = 0.f;

    for (int c = start; c < end; c += 32) {
        int idx = c + lane;
        int s = 0;
        float4 w = make_float4(0.f, 0.f, 0.f, 0.f);
        if (idx < end) {
            s = d_esrc[idx];
            float4 e4 = *reinterpret_cast<const float4*>(&d_el[s * 4]);
            float e;
            e = e4.x + ern.x; e = e > 0.f ? e : 0.2f * e; w.x = __expf(e);
            e = e4.y + ern.y; e = e > 0.f ? e : 0.2f * e; w.y = __expf(e);
            e = e4.z + ern.z; e = e > 0.f ? e : 0.2f * e; w.z = __expf(e);
            e = e4.w + ern.w; e = e > 0.f ? e : 0.2f * e; w.w = __expf(e);
            z0 += w.x; z1 += w.y; z2 += w.z; z3 += w.w;
        }
        ss[warp][lane] = s;
        sw[warp][lane] = w;
        __syncwarp();
        int cnt = end - c; if (cnt > 32) cnt = 32;
        int j = 0;
        // 4-wide batches: 4 independent LDG.64 in flight before the FMAs
        for (; j + 4 <= cnt; j += 4) {
            int sa = ss[warp][j], sb = ss[warp][j + 1];
            int sc = ss[warp][j + 2], sd = ss[warp][j + 3];
            float4 wa = sw[warp][j], wb = sw[warp][j + 1];
            float4 wc = sw[warp][j + 2], wd = sw[warp][j + 3];
            uint2 fa = *reinterpret_cast<const uint2*>(&d_fth[sa * 128 + lane * 4]);
            uint2 fb = *reinterpret_cast<const uint2*>(&d_fth[sb * 128 + lane * 4]);
            uint2 fc = *reinterpret_cast<const uint2*>(&d_fth[sc * 128 + lane * 4]);
            uint2 fd = *reinterpret_cast<const uint2*>(&d_fth[sd * 128 + lane * 4]);
            float2 a01 = __half22float2(*reinterpret_cast<__half2*>(&fa.x));
            float2 a23 = __half22float2(*reinterpret_cast<__half2*>(&fa.y));
            float2 b01 = __half22float2(*reinterpret_cast<__half2*>(&fb.x));
            float2 b23 = __half22float2(*reinterpret_cast<__half2*>(&fb.y));
            float2 c01 = __half22float2(*reinterpret_cast<__half2*>(&fc.x));
            float2 c23 = __half22float2(*reinterpret_cast<__half2*>(&fc.y));
            float2 d01 = __half22float2(*reinterpret_cast<__half2*>(&fd.x));
            float2 d23 = __half22float2(*reinterpret_cast<__half2*>(&fd.y));
            acc0 += wa.x * a01.x; acc1 += wa.y * a01.y; acc2 += wa.z * a23.x; acc3 += wa.w * a23.y;
            acc0 += wb.x * b01.x; acc1 += wb.y * b01.y; acc2 += wb.z * b23.x; acc3 += wb.w * b23.y;
            acc0 += wc.x * c01.x; acc1 += wc.y * c01.y; acc2 += wc.z * c23.x; acc3 += wc.w * c23.y;
            acc0 += wd.x * d01.x; acc1 += wd.y * d01.y; acc2 += wd.z * d23.x; acc3 += wd.w * d23.y;
        }
        for (; j < cnt; j++) {
            int s2 = ss[warp][j];
            float4 wv = sw[warp][j];
            uint2 f = *reinterpret_cast<const uint2*>(&d_fth[s2 * 128 + lane * 4]);
            float2 f01 = __half22float2(*reinterpret_cast<__half2*>(&f.x));
            float2 f23 = __half22float2(*reinterpret_cast<__half2*>(&f.y));
            acc0 += wv.x * f01.x; acc1 += wv.y * f01.y;
            acc2 += wv.z * f23.x; acc3 += wv.w * f23.y;
        }
        __syncwarp();
    }
#pragma unroll
    for (int o = 16; o > 0; o >>= 1) {
        z0 += __shfl_xor_sync(0xffffffffu, z0, o);
        z1 += __shfl_xor_sync(0xffffffffu, z1, o);
        z2 += __shfl_xor_sync(0xffffffffu, z2, o);
        z3 += __shfl_xor_sync(0xffffffffu, z3, o);
    }

    float v0 = (z0 > 0.f ? acc0 / z0 : 0.f) + bias[0 * 32 + lane];
    float v1 = (z1 > 0.f ? acc1 / z1 : 0.f) + bias[1 * 32 + lane];
    float v2 = (z2 > 0.f ? acc2 / z2 : 0.f) + bias[2 * 32 + lane];
    float v3 = (z3 > 0.f ? acc3 / z3 : 0.f) + bias[3 * 32 + lane];

    if (MODE == 0) {
        v0 = v0 > 0.f ? v0 : __expf(v0) - 1.f;
        v1 = v1 > 0.f ? v1 : __expf(v1) - 1.f;
        v2 = v2 > 0.f ? v2 : __expf(v2) - 1.f;
        v3 = v3 > 0.f ? v3 : __expf(v3) - 1.f;
        d_xh[n * 128 + 0 * 32 + lane] = __float2half(v0);
        d_xh[n * 128 + 1 * 32 + lane] = __float2half(v1);
        d_xh[n * 128 + 2 * 32 + lane] = __float2half(v2);
        d_xh[n * 128 + 3 * 32 + lane] = __float2half(v3);
    } else {
        out[n * 32 + lane] = (v0 + v1 + v2 + v3) * 0.25f;
    }
}

// ---------------- launch ----------------
extern "C" void kernel_launch(void* const* d_in, const int* in_sizes, int n_in,
                              void* d_out, int out_size) {
    const float* h   = (const float*)d_in[0];
    const int*   src = (const int*)d_in[1];
    const int*   dst = (const int*)d_in[2];
    const float* W1  = (const float*)d_in[3];
    const float* al1 = (const float*)d_in[4];
    const float* ar1 = (const float*)d_in[5];
    const float* b1  = (const float*)d_in[6];
    const float* W2  = (const float*)d_in[7];
    const float* al2 = (const float*)d_in[8];
    const float* ar2 = (const float*)d_in[9];
    const float* b2  = (const float*)d_in[10];
    const float* W3  = (const float*)d_in[11];
    const float* al3 = (const float*)d_in[12];
    const float* ar3 = (const float*)d_in[13];
    const float* b3  = (const float*)d_in[14];
    float* out = (float*)d_out;

    const int GEMM_BLOCKS = (NN + 127) / 128;
    const int NODE_BLOCKS = (NN + 7) / 8;
    const int E4_BLOCKS = (EE / 4 + 255) / 256;

    // resolve device-global base pointers for Wh (device symbol -> address)
    static __half* p_wh = nullptr;
    static cudaStream_t s2 = nullptr;
    static cudaEvent_t evFork = nullptr, evJoin = nullptr;
    if (s2 == nullptr) {
        cudaStreamCreateWithFlags(&s2, cudaStreamNonBlocking);
        cudaEventCreateWithFlags(&evFork, cudaEventDisableTiming);
        cudaEventCreateWithFlags(&evJoin, cudaEventDisableTiming);
        void* p = nullptr;
        cudaGetSymbolAddress(&p, d_wh);
        p_wh = (__half*)p;
    }

    // fork: W preconversion + layer-1 GEMM (independent of CSR build) on s2
    cudaEventRecord(evFork, 0);
    cudaStreamWaitEvent(s2, evFork, 0);
    wconv_kernel<<<(3 * FDIM * FDIM + 255) / 256, 256, 0, s2>>>(W1, W2, W3);
    gemm_tc_kernel<false><<<GEMM_BLOCKS, 256, 0, s2>>>(h, p_wh, al1, ar1);
    cudaEventRecord(evJoin, s2);

    // main stream: CSR build (reused by all 3 layers)
    count_kernel<<<E4_BLOCKS, 256>>>((const int4*)dst);
    csr_scan_emit_kernel<<<SCAN_NB, SCAN_BS>>>();
    scatter_kernel<<<E4_BLOCKS, 256>>>((const int4*)src, (const int4*)dst);

    // join: agg1 needs both CSR and GEMM1 results
    cudaStreamWaitEvent(0, evJoin, 0);
    agg_kernel<0><<<NODE_BLOCKS, 256>>>(b1, nullptr);

    // layer 2
    gemm_tc_kernel<true><<<GEMM_BLOCKS, 256>>>(nullptr, p_wh + FDIM * FDIM, al2, ar2);
    agg_kernel<0><<<NODE_BLOCKS, 256>>>(b2, nullptr);

    // layer 3
    gemm_tc_kernel<true><<<GEMM_BLOCKS, 256>>>(nullptr, p_wh + 2 * FDIM * FDIM, al3, ar3);
    agg_kernel<1><<<NODE_BLOCKS, 256>>>(b3, out);
}

// round 15
// speedup vs baseline: 1.0900x; 1.0218x over previous
#include <cuda_runtime.h>
#include <cuda_fp16.h>
#include <math.h>

#define NN 50000
#define EE 1600000
#define FDIM 128
#define NHEAD 4
#define SCAN_BS 256
#define SCAN_NB ((NN + SCAN_BS - 1) / SCAN_BS)   // 196

// PDL: allow dependents to launch early / wait for predecessor completion.
#define PDL_SIGNAL() asm volatile("griddepcontrol.launch_dependents;")
#define PDL_WAIT()   asm volatile("griddepcontrol.wait;" ::: "memory")

// ---------------- scratch (device globals, no allocation) ----------------
__device__ __half d_fth[NN * FDIM]; // transposed per-node features fp16: [n][d*4+h]
__device__ __half d_xh[NN * FDIM];  // inter-layer activations fp16: [n][h*32+d]
__device__ __half d_wh[3][FDIM * FDIM]; // fp16 W^T per layer: [n][k]
__device__ float d_el[NN * NHEAD];
__device__ float d_er[NN * NHEAD];
__device__ int   d_cnt[NN];         // zero-init; self-cleaned each run
__device__ int   d_rowptr[NN + 1];
__device__ int   d_esrc[EE];
__device__ int   d_eoff[EE];        // per-edge ticket (local offset within dst's segment)
__device__ int   d_bsum[SCAN_NB];
__device__ int   d_boff[SCAN_NB];
__device__ int   d_scan_ctr;
__device__ int   d_done_ctr;
__device__ int   d_scan_flag;

// ---------------- W preconversion: fp32 [k][n] -> fp16 transposed [n][k], all 3 layers ----------------
__global__ void wconv_kernel(const float* __restrict__ W1,
                             const float* __restrict__ W2,
                             const float* __restrict__ W3) {
    int idx = blockIdx.x * blockDim.x + threadIdx.x;   // 0 .. 3*16384-1
    if (idx < 3 * FDIM * FDIM) {
        int layer = idx >> 14;
        int rem = idx & 16383;
        int k = rem >> 7, n = rem & 127;
        const float* W = (layer == 0) ? W1 : (layer == 1) ? W2 : W3;
        d_wh[layer][n * FDIM + k] = __float2half(W[rem]);
    }
}

// ---------------- CSR build ----------------
// Count + ticket capture: the atomicAdd return value IS the edge's local
// offset within its destination segment; store it so scatter needs no atomics.
__global__ void count_kernel(const int4* __restrict__ dst4) {
    int i = blockIdx.x * blockDim.x + threadIdx.x;
    if (i < EE / 4) {
        int4 d = dst4[i];
        int4 o;
        o.x = atomicAdd(&d_cnt[d.x], 1);
        o.y = atomicAdd(&d_cnt[d.y], 1);
        o.z = atomicAdd(&d_cnt[d.z], 1);
        o.w = atomicAdd(&d_cnt[d.w], 1);
        reinterpret_cast<int4*>(d_eoff)[i] = o;
    }
}

// Fused scan+emit, grid-resident (196 blocks all fit in wave 1).
__global__ __launch_bounds__(SCAN_BS) void csr_scan_emit_kernel() {
    PDL_WAIT();   // predecessor (count) must be complete before reading d_cnt
    __shared__ int sh[SCAN_BS];
    __shared__ bool s_last;
    __shared__ int s_boff;
    int b = blockIdx.x, t = threadIdx.x;
    int i = b * SCAN_BS + t;
    int v = (i < NN) ? d_cnt[i] : 0;
    if (i < NN) d_cnt[i] = 0;        // self-clean for the next replay

    sh[t] = v;
    __syncthreads();
    for (int d = 1; d < SCAN_BS; d <<= 1) {
        int x = sh[t];
        int add = (t >= d) ? sh[t - d] : 0;
        __syncthreads();
        sh[t] = x + add;
        __syncthreads();
    }
    int incl = sh[t];
    int total = sh[SCAN_BS - 1];

    volatile int* vflag = &d_scan_flag;
    if (t == 0) {
        d_bsum[b] = total;
        __threadfence();
        int ticket = atomicAdd(&d_scan_ctr, 1);
        s_last = (ticket == SCAN_NB - 1);
    }
    __syncthreads();

    if (s_last) {
        __syncthreads();
        int x = (t < SCAN_NB) ? d_bsum[t] : 0;
        int orig = x;
        sh[t] = x;
        __syncthreads();
        for (int d = 1; d < SCAN_BS; d <<= 1) {
            int y = sh[t];
            int add = (t >= d) ? sh[t - d] : 0;
            __syncthreads();
            sh[t] = y + add;
            __syncthreads();
        }
        if (t < SCAN_NB) d_boff[t] = sh[t] - orig;   // exclusive
        if (t == SCAN_NB - 1) d_rowptr[NN] = sh[t];
        __threadfence();
        if (t == 0) *vflag = 1;
    }

    if (t == 0) {
        while (*vflag == 0) {}
        __threadfence();
        s_boff = d_boff[b];
    }
    __syncthreads();
    if (i < NN) d_rowptr[i] = s_boff + incl - v;    // exclusive prefix
    __syncthreads();
    if (t == 0) {
        int ticket2 = atomicAdd(&d_done_ctr, 1);
        if (ticket2 == SCAN_NB - 1) {
            d_scan_flag = 0;
            d_scan_ctr = 0;
            d_done_ctr = 0;
        }
    }
}

// Atomic-free scatter: destination slot = rowptr[dst] + ticket.
__global__ void scatter_kernel(const int4* __restrict__ src4, const int4* __restrict__ dst4) {
    PDL_WAIT();   // rowptr must be complete
    int i = blockIdx.x * blockDim.x + threadIdx.x;
    if (i < EE / 4) {
        int4 s = src4[i];
        int4 d = dst4[i];
        int4 o = reinterpret_cast<const int4*>(d_eoff)[i];
        d_esrc[d_rowptr[d.x] + o.x] = s.x;
        d_esrc[d_rowptr[d.y] + o.y] = s.y;
        d_esrc[d_rowptr[d.z] + o.z] = s.z;
        d_esrc[d_rowptr[d.w] + o.w] = s.w;
    }
}

// ---------------- tensor-core GEMM ----------------
__device__ __forceinline__ void mma16816(float* d,
                                         unsigned a0, unsigned a1, unsigned a2, unsigned a3,
                                         unsigned b0, unsigned b1) {
    asm volatile(
        "mma.sync.aligned.m16n8k16.row.col.f32.f16.f16.f32 "
        "{%0,%1,%2,%3}, {%4,%5,%6,%7}, {%8,%9}, {%0,%1,%2,%3};"
        : "+f"(d[0]), "+f"(d[1]), "+f"(d[2]), "+f"(d[3])
        : "r"(a0), "r"(a1), "r"(a2), "r"(a3), "r"(b0), "r"(b1));
}
__device__ __forceinline__ unsigned f2h2(float lo, float hi) {
    __half2 h = __floats2half2_rn(lo, hi);
    return *reinterpret_cast<unsigned*>(&h);
}

// ft = x @ W -> fp16 transposed [n][d*4+h], fused el/er (fp32), via HMMA m16n8k16.
// PDL: signal at top (next agg may launch; it only reads rowptr pre-wait);
// prologue (Wh copy + al/ar, independent of d_xh) overlaps predecessor agg;
// wait before the mainloop reads d_xh.
#define WSTRIDE 136
template <bool X_IS_HALF>
__global__ __launch_bounds__(256, 2) void gemm_tc_kernel(const float* __restrict__ xin,
                                                         const __half* __restrict__ Wh,
                                                         const float* __restrict__ al,
                                                         const float* __restrict__ ar) {
    PDL_SIGNAL();
    __shared__ __half Wt[128 * WSTRIDE];   // union: W^T fp16 [n][k], then per-warp staging
    __shared__ float sal[128], sar[128];
    int t = threadIdx.x;
    int w = t >> 5, l = t & 31;
    int g = l >> 2, tig = l & 3;
    int row0 = blockIdx.x * 128;

    // fp16 W^T copy: 2048 uint4 (8 halfs each)
#pragma unroll
    for (int i = 0; i < 8; i++) {
        int e = t + 256 * i;
        int n = e >> 4;             // 16 uint4 per n-row
        int k8 = (e & 15) << 3;     // k in units of 8
        uint4 v = reinterpret_cast<const uint4*>(Wh)[e];
        *reinterpret_cast<uint4*>(&Wt[n * WSTRIDE + k8]) = v;
    }
    if (t < 128) sal[t] = al[t];
    else sar[t - 128] = ar[t - 128];
    __syncthreads();
    PDL_WAIT();   // d_xh (predecessor agg output) must now be complete

    float acc[16][4];
#pragma unroll
    for (int nt = 0; nt < 16; nt++)
#pragma unroll
        for (int j = 0; j < 4; j++) acc[nt][j] = 0.f;

    int r1 = row0 + w * 16 + g;   // rows this thread's fragments cover
    int r2 = r1 + 8;
    bool ok1 = r1 < NN, ok2 = r2 < NN;

#pragma unroll
    for (int ks = 0; ks < 8; ks++) {
        int k0 = ks * 16 + 2 * tig;
        unsigned a0 = 0, a1 = 0, a2 = 0, a3 = 0;
        if (X_IS_HALF) {
            if (ok1) {
                a0 = *reinterpret_cast<const unsigned*>(&d_xh[r1 * 128 + k0]);
                a2 = *reinterpret_cast<const unsigned*>(&d_xh[r1 * 128 + k0 + 8]);
            }
            if (ok2) {
                a1 = *reinterpret_cast<const unsigned*>(&d_xh[r2 * 128 + k0]);
                a3 = *reinterpret_cast<const unsigned*>(&d_xh[r2 * 128 + k0 + 8]);
            }
        } else {
            if (ok1) {
                float2 f = *reinterpret_cast<const float2*>(&xin[r1 * 128 + k0]);
                a0 = f2h2(f.x, f.y);
                f = *reinterpret_cast<const float2*>(&xin[r1 * 128 + k0 + 8]);
                a2 = f2h2(f.x, f.y);
            }
            if (ok2) {
                float2 f = *reinterpret_cast<const float2*>(&xin[r2 * 128 + k0]);
                a1 = f2h2(f.x, f.y);
                f = *reinterpret_cast<const float2*>(&xin[r2 * 128 + k0 + 8]);
                a3 = f2h2(f.x, f.y);
            }
        }
#pragma unroll
        for (int nt = 0; nt < 16; nt++) {
            const __half* bp = &Wt[(nt * 8 + g) * WSTRIDE + k0];
            unsigned b0 = *reinterpret_cast<const unsigned*>(bp);
            unsigned b1 = *reinterpret_cast<const unsigned*>(bp + 8);
            mma16816(acc[nt], a0, a1, a2, a3, b0, b1);
        }
    }

    // fused el/er from fragments: col c = nt*8 + 2*tig (+1); head = nt>>2
    {
        float pll[4] = {0, 0, 0, 0}, plh[4] = {0, 0, 0, 0};
        float prl[4] = {0, 0, 0, 0}, prh[4] = {0, 0, 0, 0};
#pragma unroll
        for (int nt = 0; nt < 16; nt++) {
            int hh = nt >> 2;
            int c = nt * 8 + 2 * tig;
            float s0 = sal[c], s1 = sal[c + 1];
            float u0 = sar[c], u1 = sar[c + 1];
            pll[hh] += acc[nt][0] * s0 + acc[nt][1] * s1;
            plh[hh] += acc[nt][2] * s0 + acc[nt][3] * s1;
            prl[hh] += acc[nt][0] * u0 + acc[nt][1] * u1;
            prh[hh] += acc[nt][2] * u0 + acc[nt][3] * u1;
        }
#pragma unroll
        for (int o = 1; o <= 2; o <<= 1) {
#pragma unroll
            for (int hh = 0; hh < 4; hh++) {
                pll[hh] += __shfl_xor_sync(0xffffffffu, pll[hh], o);
                plh[hh] += __shfl_xor_sync(0xffffffffu, plh[hh], o);
                prl[hh] += __shfl_xor_sync(0xffffffffu, prl[hh], o);
                prh[hh] += __shfl_xor_sync(0xffffffffu, prh[hh], o);
            }
        }
        if (tig == 0) {
            if (ok1) {
                *reinterpret_cast<float4*>(&d_el[r1 * 4]) = make_float4(pll[0], pll[1], pll[2], pll[3]);
                *reinterpret_cast<float4*>(&d_er[r1 * 4]) = make_float4(prl[0], prl[1], prl[2], prl[3]);
            }
            if (ok2) {
                *reinterpret_cast<float4*>(&d_el[r2 * 4]) = make_float4(plh[0], plh[1], plh[2], plh[3]);
                *reinterpret_cast<float4*>(&d_er[r2 * 4]) = make_float4(prh[0], prh[1], prh[2], prh[3]);
            }
        }
    }

    // stage D (fp16) per warp, then write ft transposed [r][d*4+h]
    __syncthreads();   // all warps done reading Wt
    __half* stg = &Wt[w * 16 * WSTRIDE];
#pragma unroll
    for (int nt = 0; nt < 16; nt++) {
        int c = nt * 8 + 2 * tig;
        *reinterpret_cast<unsigned*>(&stg[g * WSTRIDE + c]) = f2h2(acc[nt][0], acc[nt][1]);
        *reinterpret_cast<unsigned*>(&stg[(g + 8) * WSTRIDE + c]) = f2h2(acc[nt][2], acc[nt][3]);
    }
    __syncwarp();
#pragma unroll
    for (int r = 0; r < 16; r++) {
        int rr = row0 + w * 16 + r;
        if (rr < NN) {
            __half v0 = stg[r * WSTRIDE + l];
            __half v1 = stg[r * WSTRIDE + 32 + l];
            __half v2 = stg[r * WSTRIDE + 64 + l];
            __half v3 = stg[r * WSTRIDE + 96 + l];
            __half2 p01 = __halves2half2(v0, v1);
            __half2 p23 = __halves2half2(v2, v3);
            uint2 o;
            o.x = *reinterpret_cast<unsigned*>(&p01);
            o.y = *reinterpret_cast<unsigned*>(&p23);
            *reinterpret_cast<uint2*>(&d_fth[rr * 128 + l * 4]) = o;
        }
    }
}

// ---------------- per-dst-node softmax + aggregation, single pass (no max) ----------------
// PDL: signal at top (next gemm may start its W prologue); pre-wait reads only
// rowptr (CSR, stable across layers); wait before reading er/el/fth (gemm output).
template <int MODE>
__global__ __launch_bounds__(256) void agg_kernel(const float* __restrict__ bias,
                                                  float* __restrict__ out) {
    PDL_SIGNAL();
    __shared__ float4 sw[8][32];
    __shared__ int ss[8][32];
    int warp = threadIdx.x >> 5, lane = threadIdx.x & 31;
    int n = blockIdx.x * 8 + warp;
    if (n >= NN) { PDL_WAIT(); return; }
    int start = d_rowptr[n], end = d_rowptr[n + 1];
    PDL_WAIT();   // el/er/fth (predecessor gemm output) must now be complete
    float4 ern = *reinterpret_cast<const float4*>(&d_er[n * 4]);

    float acc0 = 0.f, acc1 = 0.f, acc2 = 0.f, acc3 = 0.f;
    float z0 = 0.f, z1 = 0.f, z2 = 0.f, z3 = 0.f;

    for (int c = start; c < end; c += 32) {
        int idx = c + lane;
        int s = 0;
        float4 w = make_float4(0.f, 0.f, 0.f, 0.f);
        if (idx < end) {
            s = d_esrc[idx];
            float4 e4 = *reinterpret_cast<const float4*>(&d_el[s * 4]);
            float e;
            e = e4.x + ern.x; e = e > 0.f ? e : 0.2f * e; w.x = __expf(e);
            e = e4.y + ern.y; e = e > 0.f ? e : 0.2f * e; w.y = __expf(e);
            e = e4.z + ern.z; e = e > 0.f ? e : 0.2f * e; w.z = __expf(e);
            e = e4.w + ern.w; e = e > 0.f ? e : 0.2f * e; w.w = __expf(e);
            z0 += w.x; z1 += w.y; z2 += w.z; z3 += w.w;
        }
        ss[warp][lane] = s;
        sw[warp][lane] = w;
        __syncwarp();
        int cnt = end - c; if (cnt > 32) cnt = 32;
        int j = 0;
        // 4-wide batches: 4 independent LDG.64 in flight before the FMAs
        for (; j + 4 <= cnt; j += 4) {
            int sa = ss[warp][j], sb = ss[warp][j + 1];
            int sc = ss[warp][j + 2], sd = ss[warp][j + 3];
            float4 wa = sw[warp][j], wb = sw[warp][j + 1];
            float4 wc = sw[warp][j + 2], wd = sw[warp][j + 3];
            uint2 fa = *reinterpret_cast<const uint2*>(&d_fth[sa * 128 + lane * 4]);
            uint2 fb = *reinterpret_cast<const uint2*>(&d_fth[sb * 128 + lane * 4]);
            uint2 fc = *reinterpret_cast<const uint2*>(&d_fth[sc * 128 + lane * 4]);
            uint2 fd = *reinterpret_cast<const uint2*>(&d_fth[sd * 128 + lane * 4]);
            float2 a01 = __half22float2(*reinterpret_cast<__half2*>(&fa.x));
            float2 a23 = __half22float2(*reinterpret_cast<__half2*>(&fa.y));
            float2 b01 = __half22float2(*reinterpret_cast<__half2*>(&fb.x));
            float2 b23 = __half22float2(*reinterpret_cast<__half2*>(&fb.y));
            float2 c01 = __half22float2(*reinterpret_cast<__half2*>(&fc.x));
            float2 c23 = __half22float2(*reinterpret_cast<__half2*>(&fc.y));
            float2 d01 = __half22float2(*reinterpret_cast<__half2*>(&fd.x));
            float2 d23 = __half22float2(*reinterpret_cast<__half2*>(&fd.y));
            acc0 += wa.x * a01.x; acc1 += wa.y * a01.y; acc2 += wa.z * a23.x; acc3 += wa.w * a23.y;
            acc0 += wb.x * b01.x; acc1 += wb.y * b01.y; acc2 += wb.z * b23.x; acc3 += wb.w * b23.y;
            acc0 += wc.x * c01.x; acc1 += wc.y * c01.y; acc2 += wc.z * c23.x; acc3 += wc.w * c23.y;
            acc0 += wd.x * d01.x; acc1 += wd.y * d01.y; acc2 += wd.z * d23.x; acc3 += wd.w * d23.y;
        }
        for (; j < cnt; j++) {
            int s2 = ss[warp][j];
            float4 wv = sw[warp][j];
            uint2 f = *reinterpret_cast<const uint2*>(&d_fth[s2 * 128 + lane * 4]);
            float2 f01 = __half22float2(*reinterpret_cast<__half2*>(&f.x));
            float2 f23 = __half22float2(*reinterpret_cast<__half2*>(&f.y));
            acc0 += wv.x * f01.x; acc1 += wv.y * f01.y;
            acc2 += wv.z * f23.x; acc3 += wv.w * f23.y;
        }
        __syncwarp();
    }
#pragma unroll
    for (int o = 16; o > 0; o >>= 1) {
        z0 += __shfl_xor_sync(0xffffffffu, z0, o);
        z1 += __shfl_xor_sync(0xffffffffu, z1, o);
        z2 += __shfl_xor_sync(0xffffffffu, z2, o);
        z3 += __shfl_xor_sync(0xffffffffu, z3, o);
    }

    float v0 = (z0 > 0.f ? acc0 / z0 : 0.f) + bias[0 * 32 + lane];
    float v1 = (z1 > 0.f ? acc1 / z1 : 0.f) + bias[1 * 32 + lane];
    float v2 = (z2 > 0.f ? acc2 / z2 : 0.f) + bias[2 * 32 + lane];
    float v3 = (z3 > 0.f ? acc3 / z3 : 0.f) + bias[3 * 32 + lane];

    if (MODE == 0) {
        v0 = v0 > 0.f ? v0 : __expf(v0) - 1.f;
        v1 = v1 > 0.f ? v1 : __expf(v1) - 1.f;
        v2 = v2 > 0.f ? v2 : __expf(v2) - 1.f;
        v3 = v3 > 0.f ? v3 : __expf(v3) - 1.f;
        d_xh[n * 128 + 0 * 32 + lane] = __float2half(v0);
        d_xh[n * 128 + 1 * 32 + lane] = __float2half(v1);
        d_xh[n * 128 + 2 * 32 + lane] = __float2half(v2);
        d_xh[n * 128 + 3 * 32 + lane] = __float2half(v3);
    } else {
        out[n * 32 + lane] = (v0 + v1 + v2 + v3) * 0.25f;
    }
}

// ---------------- launch ----------------
extern "C" void kernel_launch(void* const* d_in, const int* in_sizes, int n_in,
                              void* d_out, int out_size) {
    const float* h   = (const float*)d_in[0];
    const int*   src = (const int*)d_in[1];
    const int*   dst = (const int*)d_in[2];
    const float* W1  = (const float*)d_in[3];
    const float* al1 = (const float*)d_in[4];
    const float* ar1 = (const float*)d_in[5];
    const float* b1  = (const float*)d_in[6];
    const float* W2  = (const float*)d_in[7];
    const float* al2 = (const float*)d_in[8];
    const float* ar2 = (const float*)d_in[9];
    const float* b2  = (const float*)d_in[10];
    const float* W3  = (const float*)d_in[11];
    const float* al3 = (const float*)d_in[12];
    const float* ar3 = (const float*)d_in[13];
    const float* b3  = (const float*)d_in[14];
    float* out = (float*)d_out;

    const int GEMM_BLOCKS = (NN + 127) / 128;
    const int NODE_BLOCKS = (NN + 7) / 8;
    const int E4_BLOCKS = (EE / 4 + 255) / 256;

    static __half* p_wh = nullptr;
    static cudaStream_t s2 = nullptr;
    static cudaEvent_t evFork = nullptr, evJoin = nullptr;
    if (s2 == nullptr) {
        cudaStreamCreateWithFlags(&s2, cudaStreamNonBlocking);
        cudaEventCreateWithFlags(&evFork, cudaEventDisableTiming);
        cudaEventCreateWithFlags(&evJoin, cudaEventDisableTiming);
        void* p = nullptr;
        cudaGetSymbolAddress(&p, d_wh);
        p_wh = (__half*)p;
    }

    // PDL launch config (dependent kernel may be pre-staged / launched early)
    cudaLaunchAttribute pdlAttr[1];
    pdlAttr[0].id = cudaLaunchAttributeProgrammaticStreamSerialization;
    pdlAttr[0].val.programmaticStreamSerializationAllowed = 1;
    cudaLaunchConfig_t cfg = {};
    cfg.blockDim = dim3(256, 1, 1);
    cfg.dynamicSmemBytes = 0;
    cfg.stream = 0;
    cfg.attrs = pdlAttr;
    cfg.numAttrs = 1;

    // fork: W preconversion + layer-1 GEMM (independent of CSR build) on s2
    cudaEventRecord(evFork, 0);
    cudaStreamWaitEvent(s2, evFork, 0);
    wconv_kernel<<<(3 * FDIM * FDIM + 255) / 256, 256, 0, s2>>>(W1, W2, W3);
    gemm_tc_kernel<false><<<GEMM_BLOCKS, 256, 0, s2>>>(h, p_wh, al1, ar1);
    cudaEventRecord(evJoin, s2);

    // main stream: CSR build (reused by all 3 layers); PDL chains remove gaps
    count_kernel<<<E4_BLOCKS, 256>>>((const int4*)dst);
    cfg.gridDim = dim3(SCAN_NB, 1, 1);
    cudaLaunchKernelEx(&cfg, csr_scan_emit_kernel);
    cfg.gridDim = dim3(E4_BLOCKS, 1, 1);
    cudaLaunchKernelEx(&cfg, scatter_kernel, (const int4*)src, (const int4*)dst);

    // join: agg1 needs both CSR and GEMM1 results (event wait -> no PDL here)
    cudaStreamWaitEvent(0, evJoin, 0);
    agg_kernel<0><<<NODE_BLOCKS, 256>>>(b1, (float*)nullptr);

    // layer 2 (PDL: gemm prologue overlaps agg1 tail; agg2 launches early)
    cfg.gridDim = dim3(GEMM_BLOCKS, 1, 1);
    cudaLaunchKernelEx(&cfg, gemm_tc_kernel<true>,
                       (const float*)nullptr, (const __half*)(p_wh + FDIM * FDIM), al2, ar2);
    cfg.gridDim = dim3(NODE_BLOCKS, 1, 1);
    cudaLaunchKernelEx(&cfg, agg_kernel<0>, b2, (float*)nullptr);

    // layer 3
    cfg.gridDim = dim3(GEMM_BLOCKS, 1, 1);
    cudaLaunchKernelEx(&cfg, gemm_tc_kernel<true>,
                       (const float*)nullptr, (const __half*)(p_wh + 2 * FDIM * FDIM), al3, ar3);
    cfg.gridDim = dim3(NODE_BLOCKS, 1, 1);
    cudaLaunchKernelEx(&cfg, agg_kernel<1>, b3, out);
}